// round 16
// baseline (speedup 1.0000x reference)
#include <cuda_runtime.h>
#include <cuda_bf16.h>
#include <cstdint>

// RSA_layer: B=64, U=W=128.  out[b][u] = sum_j f[j][u]*softmax_j(s[j][u]),
//   s[j][v] = f[j] . (w_hi[:,v] + wdot[v]*q),  q = f[127]  (d folded into B).
// HMMA bf16 3-term hi/lo split GEMM, k-major loop: every fragment loaded ONCE
// (a_hi/a_lo/b_hi/b_lo per k), 12 MMAs per k.  Truncation split via PRMT;
// B' pre-scaled by log2(e) -> bare ex2.approx epilogue.  Softmax fused into
// the GEMM epilogue; no-max softmax; 2 barriers.
// Grid: 64 batches x 2 v-halves = 128 CTAs, 512 threads (16 warps).

#define THREADS 512

#define A_STRIDE_B 272   // A row bytes (136 bf16): ldmatrix rows conflict-free
#define B_STRIDE_B 276   // Bt row bytes: conflict-free transpose stores
#define FT_STRIDE  133   // floats (odd); scalar reads only

#define OFF_A_HI 0
#define OFF_A_LO (128 * A_STRIDE_B)                    // 34816
#define OFF_B_HI (2 * 128 * A_STRIDE_B)                // 69632
#define OFF_B_LO (OFF_B_HI + 64 * B_STRIDE_B)          // 87296
#define OFF_FT   (OFF_B_LO + 64 * B_STRIDE_B)          // 104960 (16B aligned)
#define OFF_RED  (OFF_FT + 64 * FT_STRIDE * 4)         // 139008: se[4][64], o[4][64]
#define SMEM_BYTES (OFF_RED + 2048)                    // 141056

#define LOG2E 1.4426950408889634f

__device__ __forceinline__ uint32_t smem_u32(const void* p) {
    return (uint32_t)__cvta_generic_to_shared((void*)p);
}

__device__ __forceinline__ void ldmatrix_x4(uint32_t* a, uint32_t addr) {
    asm volatile("ldmatrix.sync.aligned.m8n8.x4.shared.b16 {%0,%1,%2,%3}, [%4];"
                 : "=r"(a[0]), "=r"(a[1]), "=r"(a[2]), "=r"(a[3]) : "r"(addr));
}

__device__ __forceinline__ void mma_16816(float* c, const uint32_t* a,
                                          uint32_t b0, uint32_t b1) {
    asm volatile(
        "mma.sync.aligned.m16n8k16.row.col.f32.bf16.bf16.f32 "
        "{%0,%1,%2,%3}, {%4,%5,%6,%7}, {%8,%9}, {%0,%1,%2,%3};"
        : "+f"(c[0]), "+f"(c[1]), "+f"(c[2]), "+f"(c[3])
        : "r"(a[0]), "r"(a[1]), "r"(a[2]), "r"(a[3]), "r"(b0), "r"(b1));
}

__device__ __forceinline__ float ex2f(float x) {
    float r;
    asm("ex2.approx.f32 %0, %1;" : "=f"(r) : "f"(x));
    return r;
}

// truncation split: hi = bf16-truncate(f), lo = trunc(f - hi)
__device__ __forceinline__ void split2(float f0, float f1,
                                       uint32_t& hp, uint32_t& lp) {
    uint32_t b0 = __float_as_uint(f0), b1 = __float_as_uint(f1);
    hp = __byte_perm(b0, b1, 0x7632);
    float l0 = f0 - __uint_as_float(b0 & 0xffff0000u);
    float l1 = f1 - __uint_as_float(b1 & 0xffff0000u);
    lp = __byte_perm(__float_as_uint(l0), __float_as_uint(l1), 0x7632);
}

__global__ __launch_bounds__(THREADS, 1)
void rsa_kernel(const float* __restrict__ input,
                const float* __restrict__ state,
                const float* __restrict__ w,
                float* __restrict__ out)
{
    extern __shared__ char sm[];
    float* fT  = (float*)(sm + OFF_FT);     // fT[ul][j] = f[j][v0+ul] (64 rows)
    float* red = (float*)(sm + OFF_RED);    // [0:256) se[g][v], [256:512) o[g][v]

    const int tid = threadIdx.x;
    const int wid = tid >> 5;
    const int lid = tid & 31;
    const int b   = blockIdx.x >> 1;
    const int v0  = (blockIdx.x & 1) * 64;
    const int hsel = v0 >> 6;                  // which lane-half owns fT rows

    const float* stateb = state + (size_t)b * 128 * 128;
    const float* inputb = input + b * 128;

    // ---- Phase 0a: stage A = f[j][u] bf16 hi/lo (PRMT split) + fT fp32 ----
    #pragma unroll
    for (int it = 0; it < 8; it++) {
        const int j = wid + it * 16;
        float4 s4 = *(const float4*)(stateb + j * 128 + 4 * lid);
        float nx = __shfl_down_sync(0xffffffffu, s4.x, 1);
        if (lid == 31) nx = inputb[j];
        float f0 = s4.y, f1 = s4.z, f2 = s4.w, f3 = nx;  // f[j][4lid..4lid+3]

        uint2 hv, lv;
        split2(f0, f1, hv.x, lv.x);
        split2(f2, f3, hv.y, lv.y);
        *(uint2*)(sm + OFF_A_HI + j * A_STRIDE_B + lid * 8) = hv;
        *(uint2*)(sm + OFF_A_LO + j * A_STRIDE_B + lid * 8) = lv;

        // fT rows for this CTA's u-window (16 owning lanes)
        if ((lid >> 4) == hsel) {
            int ul = 4 * (lid & 15);
            fT[ul * FT_STRIDE + j]       = f0;
            fT[(ul + 1) * FT_STRIDE + j] = f1;
            fT[(ul + 2) * FT_STRIDE + j] = f2;
            fT[(ul + 3) * FT_STRIDE + j] = f3;
        }
    }

    // ---- Phase 0b: stage B' = (w_hi[u][v] + wdot[v]*q[u]) * log2e, bf16 hi/lo ----
    #pragma unroll
    for (int p = tid; p < 128 * 16; p += THREADS) {
        int u = p >> 4, v4i = (p & 15) * 4;
        float qu = (u < 127) ? stateb[127 * 128 + u + 1] : inputb[127];
        float4 wv4 = *(const float4*)(w + u * 128 + v0 + v4i);
        float4 wd4 = *(const float4*)(w + 256 * 128 + v0 + v4i);
        float wv[4] = {fmaf(wd4.x, qu, wv4.x) * LOG2E,
                       fmaf(wd4.y, qu, wv4.y) * LOG2E,
                       fmaf(wd4.z, qu, wv4.z) * LOG2E,
                       fmaf(wd4.w, qu, wv4.w) * LOG2E};
        #pragma unroll
        for (int i = 0; i < 4; i++) {
            uint32_t bi = __float_as_uint(wv[i]);
            float lo = wv[i] - __uint_as_float(bi & 0xffff0000u);
            *(__nv_bfloat16*)(sm + OFF_B_HI + (v4i + i) * B_STRIDE_B + u * 2) =
                __ushort_as_bfloat16((unsigned short)(bi >> 16));
            *(__nv_bfloat16*)(sm + OFF_B_LO + (v4i + i) * B_STRIDE_B + u * 2) =
                __ushort_as_bfloat16((unsigned short)(__float_as_uint(lo) >> 16));
        }
    }
    __syncthreads();

    // ---- GEMM: warp tile = 32 j x 16 v, K=128, 3 splits, k-major loop.
    //      Each fragment loaded once per k: 4 ldmatrix + 8 LDS + 12 MMA. ----
    const int wj = (wid & 3) * 32;          // j block (group g = wid&3)
    const int wv = (wid >> 2) * 16;         // local v block

    float acc[2][2][4];
    #pragma unroll
    for (int mt = 0; mt < 2; mt++)
        #pragma unroll
        for (int n = 0; n < 2; n++)
            #pragma unroll
            for (int c = 0; c < 4; c++) acc[mt][n][c] = 0.f;

    {
        const int lrow  = lid & 15;
        const int lcolb = (lid >> 4) * 16;
        const int bn = lid >> 2;
        const int bk = (lid & 3) * 4;

        const uint32_t smb = smem_u32(sm);
        const uint32_t ahbase = smb + OFF_A_HI
                              + (uint32_t)(wj + lrow) * A_STRIDE_B + lcolb;
        const uint32_t albase = ahbase + (OFF_A_LO - OFF_A_HI);
        const char* bhbase = sm + OFF_B_HI;

        #pragma unroll
        for (int k = 0; k < 8; k++) {
            uint32_t ah0[4], ah1[4], al0[4], al1[4];
            ldmatrix_x4(ah0, ahbase + k * 32);
            ldmatrix_x4(ah1, ahbase + 16 * A_STRIDE_B + k * 32);
            ldmatrix_x4(al0, albase + k * 32);
            ldmatrix_x4(al1, albase + 16 * A_STRIDE_B + k * 32);
            #pragma unroll
            for (int n = 0; n < 2; n++) {
                const char* bh = bhbase + (wv + n * 8 + bn) * B_STRIDE_B + k * 32 + bk;
                const char* bl = bh + (OFF_B_LO - OFF_B_HI);
                uint32_t bh0 = *(const uint32_t*)bh;
                uint32_t bh1 = *(const uint32_t*)(bh + 16);
                uint32_t bl0 = *(const uint32_t*)bl;
                uint32_t bl1 = *(const uint32_t*)(bl + 16);
                mma_16816(acc[0][n], ah0, bh0, bh1);
                mma_16816(acc[1][n], ah1, bh0, bh1);
                mma_16816(acc[0][n], al0, bh0, bh1);
                mma_16816(acc[1][n], al1, bh0, bh1);
                mma_16816(acc[0][n], ah0, bl0, bl1);
                mma_16816(acc[1][n], ah1, bl0, bl1);
            }
        }
    }

    // ---- Fused epilogue: ex2 on fragments, weighted sums ----
    {
        const int er = lid >> 2;            // j row within tile
        const int ec = (lid & 3) * 2;       // v pair within tile

        float se[2][2] = {{0.f, 0.f}, {0.f, 0.f}};   // [n][v-pair elem]
        float oo[2][2] = {{0.f, 0.f}, {0.f, 0.f}};

        #pragma unroll
        for (int mt = 0; mt < 2; mt++) {
            int j0 = wj + mt * 16 + er, j8 = j0 + 8;
            #pragma unroll
            for (int n = 0; n < 2; n++) {
                int v = wv + n * 8 + ec;
                float e00 = ex2f(acc[mt][n][0]);
                float e01 = ex2f(acc[mt][n][1]);
                float e10 = ex2f(acc[mt][n][2]);
                float e11 = ex2f(acc[mt][n][3]);
                se[n][0] += e00 + e10;
                se[n][1] += e01 + e11;
                oo[n][0] = fmaf(e00, fT[v * FT_STRIDE + j0], oo[n][0]);
                oo[n][0] = fmaf(e10, fT[v * FT_STRIDE + j8], oo[n][0]);
                oo[n][1] = fmaf(e01, fT[(v + 1) * FT_STRIDE + j0], oo[n][1]);
                oo[n][1] = fmaf(e11, fT[(v + 1) * FT_STRIDE + j8], oo[n][1]);
            }
        }

        // reduce over the 8 er-lanes (lid bits 2..4)
        #pragma unroll
        for (int n = 0; n < 2; n++)
            #pragma unroll
            for (int c = 0; c < 2; c++) {
                se[n][c] += __shfl_xor_sync(0xffffffffu, se[n][c], 4);
                se[n][c] += __shfl_xor_sync(0xffffffffu, se[n][c], 8);
                se[n][c] += __shfl_xor_sync(0xffffffffu, se[n][c], 16);
                oo[n][c] += __shfl_xor_sync(0xffffffffu, oo[n][c], 4);
                oo[n][c] += __shfl_xor_sync(0xffffffffu, oo[n][c], 8);
                oo[n][c] += __shfl_xor_sync(0xffffffffu, oo[n][c], 16);
            }

        // lanes 0..3 deposit partials for this warp's j-group g = wid&3
        if (lid < 4) {
            const int g = wid & 3;
            #pragma unroll
            for (int n = 0; n < 2; n++) {
                int v = wv + n * 8 + ec;    // ec = 2*lid here
                red[g * 64 + v]           = se[n][0];
                red[g * 64 + v + 1]       = se[n][1];
                red[256 + g * 64 + v]     = oo[n][0];
                red[256 + g * 64 + v + 1] = oo[n][1];
            }
        }
    }
    __syncthreads();

    // ---- Final: sum 4 j-group partials, divide, store ----
    if (tid < 64) {
        float se = (red[tid] + red[64 + tid]) + (red[128 + tid] + red[192 + tid]);
        float o  = (red[256 + tid] + red[320 + tid]) + (red[384 + tid] + red[448 + tid]);
        out[b * 128 + v0 + tid] = __fdividef(o, se);
    }
}

extern "C" void kernel_launch(void* const* d_in, const int* in_sizes, int n_in,
                              void* d_out, int out_size)
{
    const float* input = (const float*)d_in[0];   // (64,128)
    const float* state = (const float*)d_in[1];   // (64,128,128)
    const float* w     = (const float*)d_in[2];   // (257,128); w[128:256], b unused
    float* out = (float*)d_out;                   // (64,128)

    cudaFuncSetAttribute(rsa_kernel,
                         cudaFuncAttributeMaxDynamicSharedMemorySize, SMEM_BYTES);
    rsa_kernel<<<128, THREADS, SMEM_BYTES>>>(input, state, w, out);
}

// round 17
// speedup vs baseline: 1.3910x; 1.3910x over previous
#include <cuda_runtime.h>
#include <cuda_bf16.h>
#include <cstdint>

// RSA_layer: B=64, U=W=128.  out[b][u] = sum_j f[j][u]*softmax_j(s[j][u]),
//   s[j][v] = f[j] . (w_hi[:,v] + wdot[v]*q),  q = f[127]  (d folded into B).
// HMMA bf16 3-term split GEMM (k-major, fragments loaded once).  Epilogue
// softmax is MUFU-bound -> hybrid exp: 8/thread on MUFU ex2.approx, 8/thread
// on packed f32x2 FMA polynomial; all accumulation in f32x2.  2 barriers.
// Grid: 64 batches x 2 v-halves = 128 CTAs, 512 threads (16 warps).

#define THREADS 512

#define A_STRIDE_B 272   // A row bytes (136 bf16): ldmatrix rows conflict-free
#define B_STRIDE_B 276   // Bt row bytes: conflict-free transpose stores
#define FTR_STRIDE 68    // floats per fTr row (16B-aligned rows, low conflicts)

#define OFF_A_HI 0
#define OFF_A_LO (128 * A_STRIDE_B)                    // 34816
#define OFF_B_HI (2 * 128 * A_STRIDE_B)                // 69632
#define OFF_B_LO (OFF_B_HI + 64 * B_STRIDE_B)          // 87296
#define OFF_FTR  (OFF_B_LO + 64 * B_STRIDE_B)          // 104960 (16B aligned)
#define OFF_RED  (OFF_FTR + 128 * FTR_STRIDE * 4)      // 139776: se[4][64], o[4][64]
#define SMEM_BYTES (OFF_RED + 2048)                    // 141824

#define LOG2E 1.4426950408889634f

__device__ __forceinline__ uint32_t smem_u32(const void* p) {
    return (uint32_t)__cvta_generic_to_shared((void*)p);
}

__device__ __forceinline__ void ldmatrix_x4(uint32_t* a, uint32_t addr) {
    asm volatile("ldmatrix.sync.aligned.m8n8.x4.shared.b16 {%0,%1,%2,%3}, [%4];"
                 : "=r"(a[0]), "=r"(a[1]), "=r"(a[2]), "=r"(a[3]) : "r"(addr));
}

__device__ __forceinline__ void mma_16816(float* c, const uint32_t* a,
                                          uint32_t b0, uint32_t b1) {
    asm volatile(
        "mma.sync.aligned.m16n8k16.row.col.f32.bf16.bf16.f32 "
        "{%0,%1,%2,%3}, {%4,%5,%6,%7}, {%8,%9}, {%0,%1,%2,%3};"
        : "+f"(c[0]), "+f"(c[1]), "+f"(c[2]), "+f"(c[3])
        : "r"(a[0]), "r"(a[1]), "r"(a[2]), "r"(a[3]), "r"(b0), "r"(b1));
}

__device__ __forceinline__ float ex2f(float x) {
    float r;
    asm("ex2.approx.f32 %0, %1;" : "=f"(r) : "f"(x));
    return r;
}

// ---- packed f32x2 helpers ----
__device__ __forceinline__ uint64_t pk2(float a, float b) {
    uint64_t r; asm("mov.b64 %0, {%1, %2};" : "=l"(r) : "f"(a), "f"(b)); return r;
}
__device__ __forceinline__ void upk2(uint64_t p, float& a, float& b) {
    asm("mov.b64 {%0, %1}, %2;" : "=f"(a), "=f"(b) : "l"(p));
}
__device__ __forceinline__ void upk2u(uint64_t p, uint32_t& a, uint32_t& b) {
    asm("mov.b64 {%0, %1}, %2;" : "=r"(a), "=r"(b) : "l"(p));
}
__device__ __forceinline__ uint64_t pk2u(uint32_t a, uint32_t b) {
    uint64_t r; asm("mov.b64 %0, {%1, %2};" : "=l"(r) : "r"(a), "r"(b)); return r;
}
__device__ __forceinline__ uint64_t add2(uint64_t a, uint64_t b) {
    uint64_t r; asm("add.rn.f32x2 %0, %1, %2;" : "=l"(r) : "l"(a), "l"(b)); return r;
}
__device__ __forceinline__ uint64_t fma2(uint64_t a, uint64_t b, uint64_t c) {
    uint64_t r; asm("fma.rn.f32x2 %0, %1, %2, %3;"
                    : "=l"(r) : "l"(a), "l"(b), "l"(c)); return r;
}

// truncation split: hi = bf16-truncate(f), lo = trunc(f - hi)
__device__ __forceinline__ void split2(float f0, float f1,
                                       uint32_t& hp, uint32_t& lp) {
    uint32_t b0 = __float_as_uint(f0), b1 = __float_as_uint(f1);
    hp = __byte_perm(b0, b1, 0x7632);
    float l0 = f0 - __uint_as_float(b0 & 0xffff0000u);
    float l1 = f1 - __uint_as_float(b1 & 0xffff0000u);
    lp = __byte_perm(__float_as_uint(l0), __float_as_uint(l1), 0x7632);
}

__global__ __launch_bounds__(THREADS, 1)
void rsa_kernel(const float* __restrict__ input,
                const float* __restrict__ state,
                const float* __restrict__ w,
                float* __restrict__ out)
{
    extern __shared__ char sm[];
    float* fTr = (float*)(sm + OFF_FTR);    // fTr[j][ul] = f[j][v0+ul] (128 x 68)
    float* red = (float*)(sm + OFF_RED);    // [0:256) se[g][v], [256:512) o[g][v]

    const int tid = threadIdx.x;
    const int wid = tid >> 5;
    const int lid = tid & 31;
    const int b   = blockIdx.x >> 1;
    const int v0  = (blockIdx.x & 1) * 64;
    const int hsel = v0 >> 6;                  // which lane-half owns fTr cols

    const float* stateb = state + (size_t)b * 128 * 128;
    const float* inputb = input + b * 128;

    // ---- Phase 0a: stage A = f[j][u] bf16 hi/lo (PRMT split) + fTr fp32 ----
    #pragma unroll
    for (int it = 0; it < 8; it++) {
        const int j = wid + it * 16;
        float4 s4 = *(const float4*)(stateb + j * 128 + 4 * lid);
        float nx = __shfl_down_sync(0xffffffffu, s4.x, 1);
        if (lid == 31) nx = inputb[j];
        float f0 = s4.y, f1 = s4.z, f2 = s4.w, f3 = nx;  // f[j][4lid..4lid+3]

        uint2 hv, lv;
        split2(f0, f1, hv.x, lv.x);
        split2(f2, f3, hv.y, lv.y);
        *(uint2*)(sm + OFF_A_HI + j * A_STRIDE_B + lid * 8) = hv;
        *(uint2*)(sm + OFF_A_LO + j * A_STRIDE_B + lid * 8) = lv;

        // fTr row chunk for this CTA's u-window (16 owning lanes, one STS.128)
        if ((lid >> 4) == hsel) {
            int ul = 4 * (lid & 15);
            float4 fv; fv.x = f0; fv.y = f1; fv.z = f2; fv.w = f3;
            *(float4*)(fTr + j * FTR_STRIDE + ul) = fv;
        }
    }

    // ---- Phase 0b: stage B' = (w_hi[u][v] + wdot[v]*q[u]) * log2e, bf16 hi/lo ----
    #pragma unroll
    for (int p = tid; p < 128 * 16; p += THREADS) {
        int u = p >> 4, v4i = (p & 15) * 4;
        float qu = (u < 127) ? stateb[127 * 128 + u + 1] : inputb[127];
        float4 wv4 = *(const float4*)(w + u * 128 + v0 + v4i);
        float4 wd4 = *(const float4*)(w + 256 * 128 + v0 + v4i);
        float wv[4] = {fmaf(wd4.x, qu, wv4.x) * LOG2E,
                       fmaf(wd4.y, qu, wv4.y) * LOG2E,
                       fmaf(wd4.z, qu, wv4.z) * LOG2E,
                       fmaf(wd4.w, qu, wv4.w) * LOG2E};
        #pragma unroll
        for (int i = 0; i < 4; i++) {
            uint32_t bi = __float_as_uint(wv[i]);
            float lo = wv[i] - __uint_as_float(bi & 0xffff0000u);
            *(__nv_bfloat16*)(sm + OFF_B_HI + (v4i + i) * B_STRIDE_B + u * 2) =
                __ushort_as_bfloat16((unsigned short)(bi >> 16));
            *(__nv_bfloat16*)(sm + OFF_B_LO + (v4i + i) * B_STRIDE_B + u * 2) =
                __ushort_as_bfloat16((unsigned short)(__float_as_uint(lo) >> 16));
        }
    }
    __syncthreads();

    // ---- GEMM: warp tile = 32 j x 16 v, K=128, 3 splits, k-major loop ----
    const int wj = (wid & 3) * 32;          // j block (group g = wid&3)
    const int wv = (wid >> 2) * 16;         // local v block

    float acc[2][2][4];
    #pragma unroll
    for (int mt = 0; mt < 2; mt++)
        #pragma unroll
        for (int n = 0; n < 2; n++)
            #pragma unroll
            for (int c = 0; c < 4; c++) acc[mt][n][c] = 0.f;

    {
        const int lrow  = lid & 15;
        const int lcolb = (lid >> 4) * 16;
        const int bn = lid >> 2;
        const int bk = (lid & 3) * 4;

        const uint32_t smb = smem_u32(sm);
        const uint32_t ahbase = smb + OFF_A_HI
                              + (uint32_t)(wj + lrow) * A_STRIDE_B + lcolb;
        const uint32_t albase = ahbase + (OFF_A_LO - OFF_A_HI);
        const char* bhbase = sm + OFF_B_HI;

        #pragma unroll
        for (int k = 0; k < 8; k++) {
            uint32_t ah0[4], ah1[4], al0[4], al1[4];
            ldmatrix_x4(ah0, ahbase + k * 32);
            ldmatrix_x4(ah1, ahbase + 16 * A_STRIDE_B + k * 32);
            ldmatrix_x4(al0, albase + k * 32);
            ldmatrix_x4(al1, albase + 16 * A_STRIDE_B + k * 32);
            #pragma unroll
            for (int n = 0; n < 2; n++) {
                const char* bh = bhbase + (wv + n * 8 + bn) * B_STRIDE_B + k * 32 + bk;
                const char* bl = bh + (OFF_B_LO - OFF_B_HI);
                uint32_t bh0 = *(const uint32_t*)bh;
                uint32_t bh1 = *(const uint32_t*)(bh + 16);
                uint32_t bl0 = *(const uint32_t*)bl;
                uint32_t bl1 = *(const uint32_t*)(bl + 16);
                mma_16816(acc[0][n], ah0, bh0, bh1);
                mma_16816(acc[1][n], ah1, bh0, bh1);
                mma_16816(acc[0][n], al0, bh0, bh1);
                mma_16816(acc[1][n], al1, bh0, bh1);
                mma_16816(acc[0][n], ah0, bl0, bl1);
                mma_16816(acc[1][n], ah1, bl0, bl1);
            }
        }
    }

    // ---- Fused epilogue: hybrid exp (MUFU + f32x2 poly), packed accumulation ----
    {
        const int er = lid >> 2;            // j row within tile
        const int ec = (lid & 3) * 2;       // v pair within tile

        // ex2 poly constants (Taylor deg-4, r in [-0.5,0.5]), packed
        const uint64_t PC0 = pk2(1.0f, 1.0f);
        const uint64_t PC1 = pk2(0.6931471806f, 0.6931471806f);
        const uint64_t PC2 = pk2(0.2402265070f, 0.2402265070f);
        const uint64_t PC3 = pk2(0.0555041087f, 0.0555041087f);
        const uint64_t PC4 = pk2(0.0096181291f, 0.0096181291f);
        const uint64_t PMAG = pk2(12582912.0f, 12582912.0f);    // 1.5*2^23
        const uint64_t PNMAG = pk2(-12582912.0f, -12582912.0f);
        const uint64_t PNONE = pk2(-1.0f, -1.0f);

        uint64_t se2[2] = {0u, 0u};
        uint64_t oo2[2] = {0u, 0u};

        #pragma unroll
        for (int mt = 0; mt < 2; mt++) {
            int j0 = wj + mt * 16 + er, j8 = j0 + 8;
            #pragma unroll
            for (int n = 0; n < 2; n++) {
                int vl = wv + n * 8 + ec;
                uint64_t elo, ehi;
                if (mt == 0) {
                    // MUFU half
                    elo = pk2(ex2f(acc[0][n][0]), ex2f(acc[0][n][1]));
                    ehi = pk2(ex2f(acc[0][n][2]), ex2f(acc[0][n][3]));
                } else {
                    // poly half: ex2 via magic-round + deg-4 poly + exp insert
                    #pragma unroll
                    for (int h = 0; h < 2; h++) {
                        uint64_t x2 = pk2(acc[1][n][2 * h], acc[1][n][2 * h + 1]);
                        uint64_t t2 = add2(x2, PMAG);
                        uint64_t d2 = add2(t2, PNMAG);          // t - M = round(x)
                        uint64_t r2 = fma2(d2, PNONE, x2);      // x - round(x)
                        uint64_t p2 = fma2(r2, PC4, PC3);
                        p2 = fma2(r2, p2, PC2);
                        p2 = fma2(r2, p2, PC1);
                        p2 = fma2(r2, p2, PC0);
                        uint32_t tl, th, pl, ph;
                        upk2u(t2, tl, th);
                        upk2u(p2, pl, ph);
                        uint64_t e2 = pk2u(pl + (tl << 23), ph + (th << 23));
                        if (h == 0) elo = e2; else ehi = e2;
                    }
                }
                se2[n] = add2(se2[n], add2(elo, ehi));
                uint64_t flo = *(const uint64_t*)(fTr + j0 * FTR_STRIDE + vl);
                uint64_t fhi = *(const uint64_t*)(fTr + j8 * FTR_STRIDE + vl);
                oo2[n] = fma2(elo, flo, oo2[n]);
                oo2[n] = fma2(ehi, fhi, oo2[n]);
            }
        }

        // unpack, reduce over the 8 er-lanes (lid bits 2..4)
        float se[2][2], oo[2][2];
        upk2(se2[0], se[0][0], se[0][1]);
        upk2(se2[1], se[1][0], se[1][1]);
        upk2(oo2[0], oo[0][0], oo[0][1]);
        upk2(oo2[1], oo[1][0], oo[1][1]);

        #pragma unroll
        for (int n = 0; n < 2; n++)
            #pragma unroll
            for (int c = 0; c < 2; c++) {
                se[n][c] += __shfl_xor_sync(0xffffffffu, se[n][c], 4);
                se[n][c] += __shfl_xor_sync(0xffffffffu, se[n][c], 8);
                se[n][c] += __shfl_xor_sync(0xffffffffu, se[n][c], 16);
                oo[n][c] += __shfl_xor_sync(0xffffffffu, oo[n][c], 4);
                oo[n][c] += __shfl_xor_sync(0xffffffffu, oo[n][c], 8);
                oo[n][c] += __shfl_xor_sync(0xffffffffu, oo[n][c], 16);
            }

        // lanes 0..3 deposit partials for this warp's j-group g = wid&3
        if (lid < 4) {
            const int g = wid & 3;
            #pragma unroll
            for (int n = 0; n < 2; n++) {
                int v = wv + n * 8 + ec;    // ec = 2*lid here
                red[g * 64 + v]           = se[n][0];
                red[g * 64 + v + 1]       = se[n][1];
                red[256 + g * 64 + v]     = oo[n][0];
                red[256 + g * 64 + v + 1] = oo[n][1];
            }
        }
    }
    __syncthreads();

    // ---- Final: sum 4 j-group partials, divide, store ----
    if (tid < 64) {
        float se = (red[tid] + red[64 + tid]) + (red[128 + tid] + red[192 + tid]);
        float o  = (red[256 + tid] + red[320 + tid]) + (red[384 + tid] + red[448 + tid]);
        out[b * 128 + v0 + tid] = __fdividef(o, se);
    }
}

extern "C" void kernel_launch(void* const* d_in, const int* in_sizes, int n_in,
                              void* d_out, int out_size)
{
    const float* input = (const float*)d_in[0];   // (64,128)
    const float* state = (const float*)d_in[1];   // (64,128,128)
    const float* w     = (const float*)d_in[2];   // (257,128); w[128:256], b unused
    float* out = (float*)d_out;                   // (64,128)

    cudaFuncSetAttribute(rsa_kernel,
                         cudaFuncAttributeMaxDynamicSharedMemorySize, SMEM_BYTES);
    rsa_kernel<<<128, THREADS, SMEM_BYTES>>>(input, state, w, out);
}